// round 13
// baseline (speedup 1.0000x reference)
#include <cuda_runtime.h>
#include <cuda_bf16.h>
#include <cstdint>

// SKA: spatially-varying 3x3 grouped conv.
// x: (B=8, C=64, H=128, W=128) f32
// w: (B=8, C_w=8, 9, H, W) f32
// out[b, g*8+cw, h, col] = sum_{i,j} x_pad[..., h+i-1, col+j-1] * w[b, cw, i*3+j, h, col]
//
// Warp-tile = (b, cw, h-QUAD): one warp computes ALL 8 groups x 4 output rows.
//  - x rows per group: 6 (h0-1..h0+4) shared by 4 output rows (1.5x logical reads)
//  - 36 per-pixel weight float4s loaded ONCE per warp, reused by all 8 groups
//  -> 84 warp-LDGs per 4 output rows vs 100 in the 2-row variant (-16%).
// L2 policy (proven R10/R12): loads evict_last (x+w=71MB stays L2-resident
// across graph replays), stores evict_first (write stream = eviction victim).
// Persistent grid (456 blocks), lane = 4-wide column chunk, halo via shuffle.
// High register tile: __launch_bounds__(128,2) (~230 regs, 8 warps/SM) --
// occupancy proven non-binding (R8), read traffic proven binding (R12).

#define B_   8
#define C_   64
#define H_   128
#define W_   128
#define CW_  8
#define G_   8
#define HW_  (H_ * W_)
#define NQUADS 32
#define NTILES (B_ * CW_ * NQUADS)   // 2048 warp-tiles
#define GRID_  456

__device__ __forceinline__ float4 ldg_pol(const float* p, uint64_t pol) {
    float4 v;
    asm volatile("ld.global.nc.L2::cache_hint.v4.f32 {%0,%1,%2,%3}, [%4], %5;"
                 : "=f"(v.x), "=f"(v.y), "=f"(v.z), "=f"(v.w)
                 : "l"(p), "l"(pol));
    return v;
}

__device__ __forceinline__ void stg_pol(float* p, float4 v, uint64_t pol) {
    asm volatile("st.global.L2::cache_hint.v4.f32 [%0], {%1,%2,%3,%4}, %5;"
                 :: "l"(p), "f"(v.x), "f"(v.y), "f"(v.z), "f"(v.w), "l"(pol)
                 : "memory");
}

// accumulate one x-row's 3-tap contribution into acc (4 output columns)
__device__ __forceinline__ void row_fma(
    float4 vd, float L, float R,
    float4 wl, float4 wc, float4 wr, float4& a)
{
    a.x = fmaf(L,    wl.x, a.x);
    a.x = fmaf(vd.x, wc.x, a.x);
    a.x = fmaf(vd.y, wr.x, a.x);

    a.y = fmaf(vd.x, wl.y, a.y);
    a.y = fmaf(vd.y, wc.y, a.y);
    a.y = fmaf(vd.z, wr.y, a.y);

    a.z = fmaf(vd.y, wl.z, a.z);
    a.z = fmaf(vd.z, wc.z, a.z);
    a.z = fmaf(vd.w, wr.z, a.z);

    a.w = fmaf(vd.z, wl.w, a.w);
    a.w = fmaf(vd.w, wc.w, a.w);
    a.w = fmaf(R,    wr.w, a.w);
}

__global__ void __launch_bounds__(128, 2) ska_kernel(
    const float* __restrict__ x,
    const float* __restrict__ w,
    float* __restrict__ out)
{
    const int tid  = threadIdx.x;
    const int lane = tid & 31;
    const int q    = tid >> 5;
    const int col0 = lane << 2;
    const int wstride = GRID_ * 4;

    uint64_t pol_el, pol_ef;
    asm volatile("createpolicy.fractional.L2::evict_last.b64 %0, 1.0;"  : "=l"(pol_el));
    asm volatile("createpolicy.fractional.L2::evict_first.b64 %0, 1.0;" : "=l"(pol_ef));

    const float4 z4 = make_float4(0.f, 0.f, 0.f, 0.f);

    for (int t = blockIdx.x * 4 + q; t < NTILES; t += wstride) {
        int hq = t & 31;
        int cw = (t >> 5) & 7;
        int b  = t >> 8;
        int h0 = hq << 2;              // output rows h0 .. h0+3

        const bool top = (h0 > 0);
        const bool bot = (h0 < H_ - 4);

        // ---- 36 per-pixel weights: 9 per output row ----
        const float* wb = w + ((size_t)(b * CW_ + cw) * 9) * HW_ + h0 * W_ + col0;
        float4 wv[4][9];
#pragma unroll
        for (int k = 0; k < 9; k++) {
#pragma unroll
            for (int r = 0; r < 4; r++) {
                wv[r][k] = ldg_pol(wb + (size_t)k * HW_ + r * W_, pol_el);
            }
        }

        const float* xb = x + (size_t)b * C_ * HW_ + h0 * W_ + col0;
        float* ob = out + (size_t)b * C_ * HW_ + h0 * W_ + col0;

        // ---- groups in batches of 2 (12 independent loads per batch) ----
#pragma unroll
        for (int gg = 0; gg < G_; gg += 2) {
            float4 v[2][6];   // x rows h0-1 .. h0+4
#pragma unroll
            for (int p = 0; p < 2; p++) {
                int c = (gg + p) * CW_ + cw;
                const float* xr = xb + (size_t)c * HW_;
                v[p][0] = top ? ldg_pol(xr - W_,     pol_el) : z4;
                v[p][1] =       ldg_pol(xr,          pol_el);
                v[p][2] =       ldg_pol(xr + W_,     pol_el);
                v[p][3] =       ldg_pol(xr + 2 * W_, pol_el);
                v[p][4] =       ldg_pol(xr + 3 * W_, pol_el);
                v[p][5] = bot ? ldg_pol(xr + 4 * W_, pol_el) : z4;
            }

#pragma unroll
            for (int p = 0; p < 2; p++) {
                int c = (gg + p) * CW_ + cw;
                float* op = ob + (size_t)c * HW_;

                // halo per x-row, computed once, shared by all output rows
                float L[6], R[6];
#pragma unroll
                for (int r = 0; r < 6; r++) {
                    L[r] = __shfl_up_sync(0xffffffffu, v[p][r].w, 1);
                    R[r] = __shfl_down_sync(0xffffffffu, v[p][r].x, 1);
                    if (lane == 0)  L[r] = 0.f;
                    if (lane == 31) R[r] = 0.f;
                }

#pragma unroll
                for (int r = 0; r < 4; r++) {
                    float4 a = z4;
                    row_fma(v[p][r],     L[r],     R[r],     wv[r][0], wv[r][1], wv[r][2], a);
                    row_fma(v[p][r + 1], L[r + 1], R[r + 1], wv[r][3], wv[r][4], wv[r][5], a);
                    row_fma(v[p][r + 2], L[r + 2], R[r + 2], wv[r][6], wv[r][7], wv[r][8], a);
                    stg_pol(op + r * W_, a, pol_ef);
                }
            }
        }
    }
}

extern "C" void kernel_launch(void* const* d_in, const int* in_sizes, int n_in,
                              void* d_out, int out_size) {
    const float* x = (const float*)d_in[0];
    const float* w = (const float*)d_in[1];
    float* out = (float*)d_out;

    ska_kernel<<<GRID_, 128>>>(x, w, out);
}

// round 14
// speedup vs baseline: 1.0240x; 1.0240x over previous
#include <cuda_runtime.h>
#include <cuda_bf16.h>
#include <cstdint>

// SKA: spatially-varying 3x3 grouped conv.
// x: (B=8, C=64, H=128, W=128) f32
// w: (B=8, C_w=8, 9, H, W) f32
// out[b, g*8+cw, h, col] = sum_{i,j} x_pad[..., h+i-1, col+j-1] * w[b, cw, i*3+j, h, col]
//
// R12 tile (proven best): warp-tile = (b, cw, h-pair), one warp computes all
// 8 groups x 2 output rows; 4 x-rows per group shared by both output rows;
// 18 weight float4s loaded once per warp, reused across all 8 groups.
// L2 policy: loads evict_last (x+w stays L2-resident across graph replays),
// stores evict_first (write stream is the eviction victim).
//
// NEW (R14): perfect load balance. 4096 tiles / 2048 warps = exactly 2 tiles
// per warp (R12 had 2.246 -> ~33% wasted warp-slots in the tail). 64-thread
// blocks x 1024, __launch_bounds__(64,7) caps regs at 146 so all 2048 warps
// are resident (14 warps/SM).

#define B_   8
#define C_   64
#define H_   128
#define W_   128
#define CW_  8
#define G_   8
#define HW_  (H_ * W_)
#define NPAIRS 64
#define NTILES (B_ * CW_ * NPAIRS)   // 4096 warp-tiles
#define GRID_  1024                  // x 2 warps = 2048 warps, 2 tiles each

__device__ __forceinline__ float4 ldg_pol(const float* p, uint64_t pol) {
    float4 v;
    asm volatile("ld.global.nc.L2::cache_hint.v4.f32 {%0,%1,%2,%3}, [%4], %5;"
                 : "=f"(v.x), "=f"(v.y), "=f"(v.z), "=f"(v.w)
                 : "l"(p), "l"(pol));
    return v;
}

__device__ __forceinline__ void stg_pol(float* p, float4 v, uint64_t pol) {
    asm volatile("st.global.L2::cache_hint.v4.f32 [%0], {%1,%2,%3,%4}, %5;"
                 :: "l"(p), "f"(v.x), "f"(v.y), "f"(v.z), "f"(v.w), "l"(pol)
                 : "memory");
}

// accumulate one x-row's 3-tap contribution into acc (4 output columns)
__device__ __forceinline__ void row_fma(
    float4 vd, float L, float R,
    float4 wl, float4 wc, float4 wr, float4& a)
{
    a.x = fmaf(L,    wl.x, a.x);
    a.x = fmaf(vd.x, wc.x, a.x);
    a.x = fmaf(vd.y, wr.x, a.x);

    a.y = fmaf(vd.x, wl.y, a.y);
    a.y = fmaf(vd.y, wc.y, a.y);
    a.y = fmaf(vd.z, wr.y, a.y);

    a.z = fmaf(vd.y, wl.z, a.z);
    a.z = fmaf(vd.z, wc.z, a.z);
    a.z = fmaf(vd.w, wr.z, a.z);

    a.w = fmaf(vd.z, wl.w, a.w);
    a.w = fmaf(vd.w, wc.w, a.w);
    a.w = fmaf(R,    wr.w, a.w);
}

__global__ void __launch_bounds__(64, 7) ska_kernel(
    const float* __restrict__ x,
    const float* __restrict__ w,
    float* __restrict__ out)
{
    const int tid  = threadIdx.x;
    const int lane = tid & 31;
    const int q    = tid >> 5;          // warp in block: 0 or 1
    const int col0 = lane << 2;
    const int wstride = GRID_ * 2;      // 2048 warps

    uint64_t pol_el, pol_ef;
    asm volatile("createpolicy.fractional.L2::evict_last.b64 %0, 1.0;"  : "=l"(pol_el));
    asm volatile("createpolicy.fractional.L2::evict_first.b64 %0, 1.0;" : "=l"(pol_ef));

    const float4 z4 = make_float4(0.f, 0.f, 0.f, 0.f);

    for (int t = blockIdx.x * 2 + q; t < NTILES; t += wstride) {
        int hp = t & 63;
        int cw = (t >> 6) & 7;
        int b  = t >> 9;
        int h0 = hp << 1;              // output rows h0, h0+1

        const bool top = (h0 > 0);
        const bool bot = (h0 < H_ - 2);

        // ---- 18 per-pixel weights: 9 for row h0, 9 for row h0+1 ----
        const float* wb = w + ((size_t)(b * CW_ + cw) * 9) * HW_ + h0 * W_ + col0;
        float4 wv0[9], wv1[9];
#pragma unroll
        for (int k = 0; k < 9; k++) {
            wv0[k] = ldg_pol(wb + (size_t)k * HW_,      pol_el);
            wv1[k] = ldg_pol(wb + (size_t)k * HW_ + W_, pol_el);
        }

        const float* xb = x + (size_t)b * C_ * HW_ + h0 * W_ + col0;
        float* ob = out + (size_t)b * C_ * HW_ + h0 * W_ + col0;

        // ---- groups in batches of 2 (8 independent loads per batch) ----
#pragma unroll
        for (int gg = 0; gg < G_; gg += 2) {
            float4 v[2][4];   // x rows h0-1, h0, h0+1, h0+2
#pragma unroll
            for (int p = 0; p < 2; p++) {
                int c = (gg + p) * CW_ + cw;
                const float* xr = xb + (size_t)c * HW_;
                v[p][0] = top ? ldg_pol(xr - W_,     pol_el) : z4;
                v[p][1] =       ldg_pol(xr,          pol_el);
                v[p][2] =       ldg_pol(xr + W_,     pol_el);
                v[p][3] = bot ? ldg_pol(xr + 2 * W_, pol_el) : z4;
            }

#pragma unroll
            for (int p = 0; p < 2; p++) {
                float L[4], R[4];
#pragma unroll
                for (int r = 0; r < 4; r++) {
                    L[r] = __shfl_up_sync(0xffffffffu, v[p][r].w, 1);
                    R[r] = __shfl_down_sync(0xffffffffu, v[p][r].x, 1);
                    if (lane == 0)  L[r] = 0.f;
                    if (lane == 31) R[r] = 0.f;
                }

                float4 a0 = z4, a1 = z4;
                row_fma(v[p][0], L[0], R[0], wv0[0], wv0[1], wv0[2], a0);
                row_fma(v[p][1], L[1], R[1], wv0[3], wv0[4], wv0[5], a0);
                row_fma(v[p][2], L[2], R[2], wv0[6], wv0[7], wv0[8], a0);

                row_fma(v[p][1], L[1], R[1], wv1[0], wv1[1], wv1[2], a1);
                row_fma(v[p][2], L[2], R[2], wv1[3], wv1[4], wv1[5], a1);
                row_fma(v[p][3], L[3], R[3], wv1[6], wv1[7], wv1[8], a1);

                int c = (gg + p) * CW_ + cw;
                float* op = ob + (size_t)c * HW_;
                stg_pol(op,      a0, pol_ef);
                stg_pol(op + W_, a1, pol_ef);
            }
        }
    }
}

extern "C" void kernel_launch(void* const* d_in, const int* in_sizes, int n_in,
                              void* d_out, int out_size) {
    const float* x = (const float*)d_in[0];
    const float* w = (const float*)d_in[1];
    float* out = (float*)d_out;

    ska_kernel<<<GRID_, 64>>>(x, w, out);
}